// round 15
// baseline (speedup 1.0000x reference)
#include <cuda_runtime.h>
#include <cuda_fp16.h>
#include <math.h>

// ROI align (14x14 bilinear) + 2x2 maxpool -> (B,N,C,7,7)
// B=4, N=512, C=256, Hf=Wf=50, fx=fy=0.0625. Box: x,y<=22, w,h in [5,22].
//
// Prepass (160 CTAs: 64 positions x all 256 channels, 4-chunk loop):
// features (B,C,H,W) f32 -> g_feat16 (B,H,W,C) fp16 (512 B / position).
// Main (round-11 verbatim): per-CTA precompute 196 grid-point metas
// {int4 corner byte-offsets, uint4 half2 weights}; warp = pooled position,
// lane = 8-ch slice; software-pipelined over the 4 grid points of each pool
// cell (prefetch next meta + 4 LDG.128 before current HFMA2 chain).

#define BB 4
#define NN 512
#define CC 256
#define HF 50
#define WF 50
#define HW (HF * WF)
#define OSH 258              // s_out row stride in halves (516 B = 129 words, odd)
#define POSB 512             // bytes per spatial position in g_feat16

__device__ __align__(128) __half g_feat16[BB * HW * CC];

__device__ __forceinline__ unsigned h2_as_u32(__half2 h) { return *(unsigned*)&h; }
__device__ __forceinline__ __half2 u32_as_h2(unsigned u) { return *(__half2*)&u; }

// ---------------- prepass: (b,c,hw) f32 -> (b,hw,c) fp16 ----------------
// One CTA per (64-position tile, image); loops over 4 chunks of 64 channels.
__global__ __launch_bounds__(256)
void transpose_kernel(const float* __restrict__ features)
{
    __shared__ __half tile[64][66];
    const int hw0 = blockIdx.x * 64;
    const int b   = blockIdx.y;
    const int tx = threadIdx.x, ty = threadIdx.y;   // 32 x 8
    const int pos = 2 * tx;

    for (int c0 = 0; c0 < CC; c0 += 64) {
        const float* src = features + ((long)b * CC + c0) * HW + hw0;
        #pragma unroll
        for (int k = 0; k < 64; k += 8) {
            const int c = k + ty;
            if (hw0 + pos + 1 < HW) {
                const float2 v = *(const float2*)(src + (long)c * HW + pos);
                tile[pos][c]     = __float2half(v.x);
                tile[pos + 1][c] = __float2half(v.y);
            } else if (hw0 + pos < HW) {
                tile[pos][c] = __float2half(src[(long)c * HW + pos]);
            }
        }
        __syncthreads();

        __half* dst = g_feat16 + ((long)b * HW + hw0) * CC + c0;
        #pragma unroll
        for (int k = 0; k < 64; k += 8) {
            const int hw = k + ty;
            if (hw0 + hw < HW) {
                const __half2 v = *(const __half2*)&tile[hw][2 * tx];
                *(__half2*)(dst + (long)hw * CC + 2 * tx) = v;
            }
        }
        __syncthreads();
    }
}

// ---------------- main kernel (round-11 verbatim) ----------------
__global__ __launch_bounds__(256, 4)
void roi_align_pool_kernel(const float* __restrict__ proposals,
                           float* __restrict__ out)
{
    __shared__ int    s_box[4];
    __shared__ int    s_rl[14], s_rh[14];   // (x + row_low/high) * WF * POSB
    __shared__ int    s_cl[14], s_ch[14];   // (y + col_low/high) * POSB
    __shared__ float  s_rf[14], s_cf[14];
    __shared__ int4   s_goff[196];          // per grid point: 4 corner byte offsets
    __shared__ uint4  s_gwt[196];           // per grid point: 4 half2 weights (dup)
    __shared__ __half s_out[49 * OSH];      // [p][c], 25.3 KB

    const int bn  = blockIdx.x;
    const int b   = bn >> 9;
    const int tid = threadIdx.x;
    const int warp = tid >> 5, lane = tid & 31;

    if (tid < 4) s_box[tid] = (int)(proposals[bn * 4 + tid] * 0.0625f);
    __syncthreads();
    const int x = s_box[0], y = s_box[1], w = s_box[2], h = s_box[3];

    if (tid < 28) {
        const bool  isRow = tid < 14;
        const int   ii    = isRow ? tid : tid - 14;
        const int   len   = isRow ? w : h;
        const float scale = (float)(len - 1) / 13.0f;
        const float c     = (float)ii * scale;
        const int   low   = (int)floorf(c);
        const float frac  = c - (float)low;
        const int   high  = min(low + 1, len - 1);
        if (isRow) {
            s_rl[ii] = (x + low) * (WF * POSB);
            s_rh[ii] = (x + high) * (WF * POSB);
            s_rf[ii] = frac;
        } else {
            s_cl[ii] = (y + low) * POSB;
            s_ch[ii] = (y + high) * POSB;
            s_cf[ii] = frac;
        }
    }
    __syncthreads();

    // ---- precompute per-grid-point meta (196 points) ----
    if (tid < 196) {
        const int i = tid / 14;
        const int j = tid - i * 14;
        const int rl = s_rl[i], rh = s_rh[i];
        const int cl = s_cl[j], ch = s_ch[j];
        s_goff[tid] = make_int4(rl + cl, rl + ch, rh + cl, rh + ch);
        const float rf = s_rf[i], cf = s_cf[j];
        const float irf = 1.0f - rf, icf = 1.0f - cf;
        uint4 wv;
        wv.x = h2_as_u32(__float2half2_rn(irf * icf));
        wv.y = h2_as_u32(__float2half2_rn(irf * cf));
        wv.z = h2_as_u32(__float2half2_rn(rf * icf));
        wv.w = h2_as_u32(__float2half2_rn(rf * cf));
        s_gwt[tid] = wv;
    }
    __syncthreads();

    const char* __restrict__ base =
        (const char*)(g_feat16 + (long)b * HW * CC) + lane * 16;   // 8-ch slice

    // ---- compute: warp = pooled position, lane = 8-channel slice ----
    for (int p = warp; p < 49; p += 8) {
        const int pi = p / 7;
        const int pj = p - pi * 7;
        const int gbase = 28 * pi + 2 * pj;

        // grid-point order within pool cell: +0, +1, +14, +15
        int4  o_cur = s_goff[gbase];
        uint4 w_cur = s_gwt[gbase];
        uint4 qa = *(const uint4*)(base + o_cur.x);
        uint4 qb = *(const uint4*)(base + o_cur.y);
        uint4 qc = *(const uint4*)(base + o_cur.z);
        uint4 qd = *(const uint4*)(base + o_cur.w);

        __half2 m0, m1, m2, m3;
        #pragma unroll
        for (int dg = 0; dg < 4; dg++) {
            const uint4 w_use = w_cur;
            const uint4 ua = qa, ub = qb, uc = qc, ud = qd;

            if (dg < 3) {   // prefetch next grid point (meta + 4 corner loads)
                const int step = (dg == 0) ? 1 : ((dg == 1) ? 14 : 15);
                const int gg = gbase + step;
                const int4 o_n = s_goff[gg];
                w_cur = s_gwt[gg];
                qa = *(const uint4*)(base + o_n.x);
                qb = *(const uint4*)(base + o_n.y);
                qc = *(const uint4*)(base + o_n.z);
                qd = *(const uint4*)(base + o_n.w);
            }

            const __half2 W00 = u32_as_h2(w_use.x);
            const __half2 W01 = u32_as_h2(w_use.y);
            const __half2 W10 = u32_as_h2(w_use.z);
            const __half2 W11 = u32_as_h2(w_use.w);

            const __half2* h00 = (const __half2*)&ua;
            const __half2* h01 = (const __half2*)&ub;
            const __half2* h10 = (const __half2*)&uc;
            const __half2* h11 = (const __half2*)&ud;

            __half2 v0 = __hmul2(W00, h00[0]);
            __half2 v1 = __hmul2(W00, h00[1]);
            __half2 v2 = __hmul2(W00, h00[2]);
            __half2 v3 = __hmul2(W00, h00[3]);
            v0 = __hfma2(W01, h01[0], v0); v1 = __hfma2(W01, h01[1], v1);
            v2 = __hfma2(W01, h01[2], v2); v3 = __hfma2(W01, h01[3], v3);
            v0 = __hfma2(W10, h10[0], v0); v1 = __hfma2(W10, h10[1], v1);
            v2 = __hfma2(W10, h10[2], v2); v3 = __hfma2(W10, h10[3], v3);
            v0 = __hfma2(W11, h11[0], v0); v1 = __hfma2(W11, h11[1], v1);
            v2 = __hfma2(W11, h11[2], v2); v3 = __hfma2(W11, h11[3], v3);

            if (dg == 0) { m0 = v0; m1 = v1; m2 = v2; m3 = v3; }
            else {
                m0 = __hmax2(m0, v0); m1 = __hmax2(m1, v1);
                m2 = __hmax2(m2, v2); m3 = __hmax2(m3, v3);
            }
        }

        __half2* dst = (__half2*)(s_out + p * OSH + lane * 8);
        dst[0] = m0; dst[1] = m1; dst[2] = m2; dst[3] = m3;
    }
    __syncthreads();

    // ---- writeout: half2 LDS + two coalesced STG streams ----
    const long obase = (long)bn * (CC * 49);
    int cp = tid / 49;                  // channel pair
    int p  = tid - cp * 49;
    for (int idx = tid; idx < 128 * 49; idx += 256) {
        const __half2 v = *(const __half2*)(s_out + p * OSH + 2 * cp);
        const float2 f = __half22float2(v);
        const long o = obase + (long)(2 * cp) * 49 + p;
        out[o]      = f.x;
        out[o + 49] = f.y;
        p += 11; cp += 5;               // 256 = 5*49 + 11
        if (p >= 49) { p -= 49; cp += 1; }
    }
}

extern "C" void kernel_launch(void* const* d_in, const int* in_sizes, int n_in,
                              void* d_out, int out_size)
{
    const float* proposals = (const float*)d_in[0];   // (B,N,4) f32
    const float* features  = (const float*)d_in[1];   // (B,C,Hf,Wf) f32
    float* out = (float*)d_out;                       // (B,N,C,7,7) f32
    (void)in_sizes; (void)n_in; (void)out_size;

    dim3 tgrid((HW + 63) / 64, BB);
    dim3 tblock(32, 8);
    transpose_kernel<<<tgrid, tblock>>>(features);

    roi_align_pool_kernel<<<BB * NN, 256>>>(proposals, out);
}

// round 17
// speedup vs baseline: 1.3371x; 1.3371x over previous
#include <cuda_runtime.h>
#include <cuda_fp16.h>
#include <math.h>

// ROI align (14x14 bilinear) + 2x2 maxpool -> (B,N,C,7,7)
// B=4, N=512, C=256, Hf=Wf=50, fx=fy=0.0625. Box: x,y<=22, w,h in [5,22].
//
// Prepass (64x64 tiles, 640 CTAs): features (B,C,H,W) f32 -> g_feat16
// (B,H,W,C) fp16 (512 B / position).
// Main: round-11 hot loop verbatim; writeout vectorized (LDS.128 = 8 channels
// of one position per thread, then 8 coalesced STG.32 streams).
// OSH = 264 halves (528 B = 33x16B): 16B-aligned rows for LDS.128; slot
// stride 33 mod 8 = 1 -> conflict-free phases.

#define BB 4
#define NN 512
#define CC 256
#define HF 50
#define WF 50
#define HW (HF * WF)
#define OSH 264              // s_out row stride in halves (528 B, 16B-aligned)
#define POSB 512             // bytes per spatial position in g_feat16

__device__ __align__(128) __half g_feat16[BB * HW * CC];

__device__ __forceinline__ unsigned h2_as_u32(__half2 h) { return *(unsigned*)&h; }
__device__ __forceinline__ __half2 u32_as_h2(unsigned u) { return *(__half2*)&u; }

// ---------------- prepass: (b,c,hw) f32 -> (b,hw,c) fp16 ----------------
__global__ __launch_bounds__(256)
void transpose_kernel(const float* __restrict__ features)
{
    __shared__ __half tile[64][66];
    const int hw0 = blockIdx.x * 64;
    const int c0  = blockIdx.y * 64;
    const int b   = blockIdx.z;
    const int tx = threadIdx.x, ty = threadIdx.y;   // 32 x 8

    const float* src = features + ((long)b * CC + c0) * HW + hw0;
    const int pos = 2 * tx;
    #pragma unroll
    for (int k = 0; k < 64; k += 8) {
        const int c = k + ty;
        if (hw0 + pos + 1 < HW) {
            const float2 v = *(const float2*)(src + (long)c * HW + pos);
            tile[pos][c]     = __float2half(v.x);
            tile[pos + 1][c] = __float2half(v.y);
        } else if (hw0 + pos < HW) {
            tile[pos][c] = __float2half(src[(long)c * HW + pos]);
        }
    }
    __syncthreads();

    __half* dst = g_feat16 + ((long)b * HW + hw0) * CC + c0;
    #pragma unroll
    for (int k = 0; k < 64; k += 8) {
        const int hw = k + ty;
        if (hw0 + hw < HW) {
            const __half2 v = *(const __half2*)&tile[hw][2 * tx];
            *(__half2*)(dst + (long)hw * CC + 2 * tx) = v;
        }
    }
}

// ---------------- main kernel ----------------
__global__ __launch_bounds__(256, 4)
void roi_align_pool_kernel(const float* __restrict__ proposals,
                           float* __restrict__ out)
{
    __shared__ int    s_box[4];
    __shared__ int    s_rl[14], s_rh[14];   // (x + row_low/high) * WF * POSB
    __shared__ int    s_cl[14], s_ch[14];   // (y + col_low/high) * POSB
    __shared__ float  s_rf[14], s_cf[14];
    __shared__ int4   s_goff[196];          // per grid point: 4 corner byte offsets
    __shared__ uint4  s_gwt[196];           // per grid point: 4 half2 weights (dup)
    __shared__ __align__(16) __half s_out[49 * OSH];   // [p][c], 25.9 KB

    const int bn  = blockIdx.x;
    const int b   = bn >> 9;
    const int tid = threadIdx.x;
    const int warp = tid >> 5, lane = tid & 31;

    if (tid < 4) s_box[tid] = (int)(proposals[bn * 4 + tid] * 0.0625f);
    __syncthreads();
    const int x = s_box[0], y = s_box[1], w = s_box[2], h = s_box[3];

    if (tid < 28) {
        const bool  isRow = tid < 14;
        const int   ii    = isRow ? tid : tid - 14;
        const int   len   = isRow ? w : h;
        const float scale = (float)(len - 1) / 13.0f;
        const float c     = (float)ii * scale;
        const int   low   = (int)floorf(c);
        const float frac  = c - (float)low;
        const int   high  = min(low + 1, len - 1);
        if (isRow) {
            s_rl[ii] = (x + low) * (WF * POSB);
            s_rh[ii] = (x + high) * (WF * POSB);
            s_rf[ii] = frac;
        } else {
            s_cl[ii] = (y + low) * POSB;
            s_ch[ii] = (y + high) * POSB;
            s_cf[ii] = frac;
        }
    }
    __syncthreads();

    // ---- precompute per-grid-point meta (196 points) ----
    if (tid < 196) {
        const int i = tid / 14;
        const int j = tid - i * 14;
        const int rl = s_rl[i], rh = s_rh[i];
        const int cl = s_cl[j], ch = s_ch[j];
        s_goff[tid] = make_int4(rl + cl, rl + ch, rh + cl, rh + ch);
        const float rf = s_rf[i], cf = s_cf[j];
        const float irf = 1.0f - rf, icf = 1.0f - cf;
        uint4 wv;
        wv.x = h2_as_u32(__float2half2_rn(irf * icf));
        wv.y = h2_as_u32(__float2half2_rn(irf * cf));
        wv.z = h2_as_u32(__float2half2_rn(rf * icf));
        wv.w = h2_as_u32(__float2half2_rn(rf * cf));
        s_gwt[tid] = wv;
    }
    __syncthreads();

    const char* __restrict__ base =
        (const char*)(g_feat16 + (long)b * HW * CC) + lane * 16;   // 8-ch slice

    // ---- compute: warp = pooled position, lane = 8-channel slice ----
    for (int p = warp; p < 49; p += 8) {
        const int pi = p / 7;
        const int pj = p - pi * 7;
        const int gbase = 28 * pi + 2 * pj;

        // grid-point order within pool cell: +0, +1, +14, +15
        int4  o_cur = s_goff[gbase];
        uint4 w_cur = s_gwt[gbase];
        uint4 qa = *(const uint4*)(base + o_cur.x);
        uint4 qb = *(const uint4*)(base + o_cur.y);
        uint4 qc = *(const uint4*)(base + o_cur.z);
        uint4 qd = *(const uint4*)(base + o_cur.w);

        __half2 m0, m1, m2, m3;
        #pragma unroll
        for (int dg = 0; dg < 4; dg++) {
            const uint4 w_use = w_cur;
            const uint4 ua = qa, ub = qb, uc = qc, ud = qd;

            if (dg < 3) {   // prefetch next grid point (meta + 4 corner loads)
                const int step = (dg == 0) ? 1 : ((dg == 1) ? 14 : 15);
                const int gg = gbase + step;
                const int4 o_n = s_goff[gg];
                w_cur = s_gwt[gg];
                qa = *(const uint4*)(base + o_n.x);
                qb = *(const uint4*)(base + o_n.y);
                qc = *(const uint4*)(base + o_n.z);
                qd = *(const uint4*)(base + o_n.w);
            }

            const __half2 W00 = u32_as_h2(w_use.x);
            const __half2 W01 = u32_as_h2(w_use.y);
            const __half2 W10 = u32_as_h2(w_use.z);
            const __half2 W11 = u32_as_h2(w_use.w);

            const __half2* h00 = (const __half2*)&ua;
            const __half2* h01 = (const __half2*)&ub;
            const __half2* h10 = (const __half2*)&uc;
            const __half2* h11 = (const __half2*)&ud;

            __half2 v0 = __hmul2(W00, h00[0]);
            __half2 v1 = __hmul2(W00, h00[1]);
            __half2 v2 = __hmul2(W00, h00[2]);
            __half2 v3 = __hmul2(W00, h00[3]);
            v0 = __hfma2(W01, h01[0], v0); v1 = __hfma2(W01, h01[1], v1);
            v2 = __hfma2(W01, h01[2], v2); v3 = __hfma2(W01, h01[3], v3);
            v0 = __hfma2(W10, h10[0], v0); v1 = __hfma2(W10, h10[1], v1);
            v2 = __hfma2(W10, h10[2], v2); v3 = __hfma2(W10, h10[3], v3);
            v0 = __hfma2(W11, h11[0], v0); v1 = __hfma2(W11, h11[1], v1);
            v2 = __hfma2(W11, h11[2], v2); v3 = __hfma2(W11, h11[3], v3);

            if (dg == 0) { m0 = v0; m1 = v1; m2 = v2; m3 = v3; }
            else {
                m0 = __hmax2(m0, v0); m1 = __hmax2(m1, v1);
                m2 = __hmax2(m2, v2); m3 = __hmax2(m3, v3);
            }
        }

        __half2* dst = (__half2*)(s_out + p * OSH + lane * 8);
        dst[0] = m0; dst[1] = m1; dst[2] = m2; dst[3] = m3;
    }
    __syncthreads();

    // ---- writeout: LDS.128 (8 channels of one position) + 8 coalesced STG ----
    // item = (c8, p): c8 in 0..31, p in 0..48. Consecutive tid -> consecutive p.
    {
        const long obase = (long)bn * (CC * 49);
        int c8 = tid / 49;
        int p  = tid - c8 * 49;
        for (int idx = tid; idx < 32 * 49; idx += 256) {
            const uint4 q = *(const uint4*)(s_out + p * OSH + c8 * 8);
            const float2 f0 = __half22float2(u32_as_h2(q.x));
            const float2 f1 = __half22float2(u32_as_h2(q.y));
            const float2 f2 = __half22float2(u32_as_h2(q.z));
            const float2 f3 = __half22float2(u32_as_h2(q.w));
            float* o = out + obase + (long)(c8 * 8) * 49 + p;
            o[0]       = f0.x;
            o[49]      = f0.y;
            o[98]      = f1.x;
            o[147]     = f1.y;
            o[196]     = f2.x;
            o[245]     = f2.y;
            o[294]     = f3.x;
            o[343]     = f3.y;
            p += 11; c8 += 5;           // 256 = 5*49 + 11
            if (p >= 49) { p -= 49; c8 += 1; }
        }
    }
}

extern "C" void kernel_launch(void* const* d_in, const int* in_sizes, int n_in,
                              void* d_out, int out_size)
{
    const float* proposals = (const float*)d_in[0];   // (B,N,4) f32
    const float* features  = (const float*)d_in[1];   // (B,C,Hf,Wf) f32
    float* out = (float*)d_out;                       // (B,N,C,7,7) f32
    (void)in_sizes; (void)n_in; (void)out_size;

    dim3 tgrid((HW + 63) / 64, CC / 64, BB);
    dim3 tblock(32, 8);
    transpose_kernel<<<tgrid, tblock>>>(features);

    roi_align_pool_kernel<<<BB * NN, 256>>>(proposals, out);
}